// round 3
// baseline (speedup 1.0000x reference)
#include <cuda_runtime.h>

#define NN 50000
#define NE 800000
#define FDIM 128
#define NREL 4
#define BN_EPS 1e-5f

#define TM 64
#define LDA 132
#define NBLK ((NN + TM - 1) / TM)   // 782
#define SMEM_BYTES ((TM * LDA + FDIM * FDIM) * 4)

// scratch (device globals: allocation-free per harness rules)
// float4-typed so the base is 16B-aligned -> LDG.128/STG.128 legal.
__device__ float4 g_h0[(size_t)NREL * NN * FDIM / 4];   // x + agg, per relation
__device__ float4 g_h1[(size_t)NREL * NN * FDIM / 4];   // after Linear1 (pre-BN)
__device__ float  g_sum[NREL * FDIM];
__device__ float  g_sumsq[NREL * FDIM];
__device__ float4 g_scale[NREL * FDIM / 4];
__device__ float4 g_shift[NREL * FDIM / 4];
__device__ float4 g_bias[FDIM / 4];

// ---------------------------------------------------------------------------
// h0[r][n][:] = x[n][:]   (GIN eps=0 self term), float4 vectorized
// ---------------------------------------------------------------------------
__global__ void k_init(const float* __restrict__ x) {
    int i = blockIdx.x * blockDim.x + threadIdx.x;
    const int total = NREL * NN * (FDIM / 4);
    if (i >= total) return;
    const int per = NN * (FDIM / 4);
    g_h0[i] = ((const float4*)x)[i % per];
}

__global__ void k_zero_stats() {
    int i = threadIdx.x;
    if (i < NREL * FDIM) { g_sum[i] = 0.f; g_sumsq[i] = 0.f; }
}

// ---------------------------------------------------------------------------
// scatter: h0[rel][dst][:] += x[src][:]
// edge_index / edge_type are INT32 (JAX x64 disabled downcasts int64->int32).
// one thread per (edge, 4 features): float4 gather + 4 scalar atomics,
// 128B-contiguous per 32 threads -> L2 coalesces the RED traffic
// ---------------------------------------------------------------------------
__global__ void k_scatter(const float* __restrict__ x,
                          const int* __restrict__ edge_index,
                          const int* __restrict__ edge_type) {
    long long g = (long long)blockIdx.x * blockDim.x + threadIdx.x;
    if (g >= (long long)NE * 32) return;
    int e = (int)(g >> 5);
    int q = (int)(g & 31);
    int src = edge_index[e];
    int dst = edge_index[NE + e];
    int rel = edge_type[e];
    if ((unsigned)src >= NN || (unsigned)dst >= NN || (unsigned)rel >= NREL) return;
    float4 v = ((const float4*)(x + (size_t)src * FDIM))[q];
    float* p = (float*)g_h0 + ((size_t)rel * NN + (size_t)dst) * FDIM + q * 4;
    atomicAdd(p + 0, v.x);
    atomicAdd(p + 1, v.y);
    atomicAdd(p + 2, v.z);
    atomicAdd(p + 3, v.w);
}

// ---------------------------------------------------------------------------
// GEMM1: h1[r] = h0[r] @ W1[r] + b1[r]; fused column sum/sumsq for BN stats.
// Block tile 64x128, K=128 fully resident. 256 thr, 4x8 micro-tile/thread.
// ---------------------------------------------------------------------------
__global__ void __launch_bounds__(256) k_gemm1(const float* __restrict__ W1,
                                               const float* __restrict__ b1) {
    extern __shared__ float smem[];
    float* As = smem;                  // [64][LDA]
    float* Bs = smem + TM * LDA;       // [128][128]
    const int r = blockIdx.y;
    const int n0 = blockIdx.x * TM;
    const int tid = threadIdx.x;
    const int tx = tid & 15;           // col group: cols tx*8 .. +7
    const int ty = tid >> 4;           // row group: rows ty*4 .. +3

    const float* A = (const float*)g_h0 + (size_t)r * NN * FDIM;
    const float4* B4 = (const float4*)(W1 + r * FDIM * FDIM);

#pragma unroll
    for (int i = 0; i < 16; i++)
        ((float4*)Bs)[i * 256 + tid] = B4[i * 256 + tid];

#pragma unroll
    for (int i = 0; i < 8; i++) {
        int idx = i * 256 + tid;
        int row = idx >> 5, c4 = idx & 31;
        float4 v = make_float4(0.f, 0.f, 0.f, 0.f);
        int n = n0 + row;
        if (n < NN) v = ((const float4*)(A + (size_t)n * FDIM))[c4];
        *(float4*)(As + row * LDA + c4 * 4) = v;
    }
    __syncthreads();

    float acc[4][8];
#pragma unroll
    for (int i = 0; i < 4; i++)
#pragma unroll
        for (int j = 0; j < 8; j++) acc[i][j] = 0.f;

#pragma unroll 4
    for (int k = 0; k < FDIM; k++) {
        float a[4];
#pragma unroll
        for (int i = 0; i < 4; i++) a[i] = As[(ty * 4 + i) * LDA + k];
        float4 b0 = *(const float4*)(Bs + k * FDIM + tx * 8);
        float4 b1v = *(const float4*)(Bs + k * FDIM + tx * 8 + 4);
        float b[8] = {b0.x, b0.y, b0.z, b0.w, b1v.x, b1v.y, b1v.z, b1v.w};
#pragma unroll
        for (int i = 0; i < 4; i++)
#pragma unroll
            for (int j = 0; j < 8; j++) acc[i][j] += a[i] * b[j];
    }
    __syncthreads();   // tile reads done; reuse smem for reductions

    float bias[8];
    {
        const float* b1r = b1 + r * FDIM + tx * 8;
#pragma unroll
        for (int j = 0; j < 8; j++) bias[j] = b1r[j];
    }

    float s[8], q[8];
#pragma unroll
    for (int j = 0; j < 8; j++) { s[j] = 0.f; q[j] = 0.f; }

    float* Hout = (float*)g_h1 + (size_t)r * NN * FDIM;
#pragma unroll
    for (int i = 0; i < 4; i++) {
        int n = n0 + ty * 4 + i;
        if (n < NN) {
            float v[8];
#pragma unroll
            for (int j = 0; j < 8; j++) {
                v[j] = acc[i][j] + bias[j];
                s[j] += v[j];
                q[j] += v[j] * v[j];
            }
            float4* o = (float4*)(Hout + (size_t)n * FDIM + tx * 8);
            o[0] = make_float4(v[0], v[1], v[2], v[3]);
            o[1] = make_float4(v[4], v[5], v[6], v[7]);
        }
    }

    // block-level column reduce (16 row-groups), then one atomic per column
    float* redS = As;   // [16][128]
    float* redQ = Bs;   // [16][128]
#pragma unroll
    for (int j = 0; j < 8; j++) {
        redS[ty * FDIM + tx * 8 + j] = s[j];
        redQ[ty * FDIM + tx * 8 + j] = q[j];
    }
#pragma unroll
    for (int off = 8; off > 0; off >>= 1) {
        __syncthreads();
        if (ty < off) {
#pragma unroll
            for (int j = 0; j < 8; j++) {
                int c = tx * 8 + j;
                redS[ty * FDIM + c] += redS[(ty + off) * FDIM + c];
                redQ[ty * FDIM + c] += redQ[(ty + off) * FDIM + c];
            }
        }
    }
    __syncthreads();
    if (ty == 0) {
#pragma unroll
        for (int j = 0; j < 8; j++) {
            int c = tx * 8 + j;
            atomicAdd(&g_sum[r * FDIM + c], redS[c]);
            atomicAdd(&g_sumsq[r * FDIM + c], redQ[c]);
        }
    }
}

// ---------------------------------------------------------------------------
// BN scale/shift per (r, col) + fold all output biases together
// ---------------------------------------------------------------------------
__global__ void k_bn(const float* __restrict__ gamma, const float* __restrict__ beta,
                     const float* __restrict__ b_self, const float* __restrict__ b2) {
    int i = threadIdx.x;
    if (i < NREL * FDIM) {
        const float invN = 1.f / (float)NN;
        float mean = g_sum[i] * invN;
        float var = g_sumsq[i] * invN - mean * mean;
        float sc = gamma[i] * rsqrtf(var + BN_EPS);
        ((float*)g_scale)[i] = sc;
        ((float*)g_shift)[i] = beta[i] - mean * sc;
    }
    if (i < FDIM) {
        float b = b_self[i];
#pragma unroll
        for (int r = 0; r < NREL; r++) b += b2[r * FDIM + i];
        ((float*)g_bias)[i] = b;
    }
}

// ---------------------------------------------------------------------------
// GEMM2 (K=640): out = sum_r relu(bn(h1[r])) @ W2[r]  +  x @ W_self  + g_bias
// BN-apply + ReLU fused into the A-tile load; writes d_out directly.
// ---------------------------------------------------------------------------
__global__ void __launch_bounds__(256) k_gemm2(const float* __restrict__ x,
                                               const float* __restrict__ W2,
                                               const float* __restrict__ W_self,
                                               float* __restrict__ out) {
    extern __shared__ float smem[];
    float* As = smem;
    float* Bs = smem + TM * LDA;
    const int n0 = blockIdx.x * TM;
    const int tid = threadIdx.x;
    const int tx = tid & 15;
    const int ty = tid >> 4;

    float acc[4][8];
#pragma unroll
    for (int i = 0; i < 4; i++)
#pragma unroll
        for (int j = 0; j < 8; j++) acc[i][j] = 0.f;

    for (int r = 0; r < NREL + 1; r++) {
        __syncthreads();   // previous iteration's tile reads must finish

        const float4* B4 = (r < NREL) ? (const float4*)(W2 + r * FDIM * FDIM)
                                      : (const float4*)W_self;
#pragma unroll
        for (int i = 0; i < 16; i++)
            ((float4*)Bs)[i * 256 + tid] = B4[i * 256 + tid];

        if (r < NREL) {
            const float* H = (const float*)g_h1 + (size_t)r * NN * FDIM;
            const float4* sc4 = g_scale + r * (FDIM / 4);
            const float4* sh4 = g_shift + r * (FDIM / 4);
#pragma unroll
            for (int i = 0; i < 8; i++) {
                int idx = i * 256 + tid;
                int row = idx >> 5, c4 = idx & 31;
                float4 v = make_float4(0.f, 0.f, 0.f, 0.f);
                int n = n0 + row;
                if (n < NN) {
                    v = ((const float4*)(H + (size_t)n * FDIM))[c4];
                    float4 sc = sc4[c4], sh = sh4[c4];
                    v.x = fmaxf(v.x * sc.x + sh.x, 0.f);
                    v.y = fmaxf(v.y * sc.y + sh.y, 0.f);
                    v.z = fmaxf(v.z * sc.z + sh.z, 0.f);
                    v.w = fmaxf(v.w * sc.w + sh.w, 0.f);
                }
                *(float4*)(As + row * LDA + c4 * 4) = v;
            }
        } else {
#pragma unroll
            for (int i = 0; i < 8; i++) {
                int idx = i * 256 + tid;
                int row = idx >> 5, c4 = idx & 31;
                float4 v = make_float4(0.f, 0.f, 0.f, 0.f);
                int n = n0 + row;
                if (n < NN) v = ((const float4*)(x + (size_t)n * FDIM))[c4];
                *(float4*)(As + row * LDA + c4 * 4) = v;
            }
        }
        __syncthreads();

#pragma unroll 4
        for (int k = 0; k < FDIM; k++) {
            float a[4];
#pragma unroll
            for (int i = 0; i < 4; i++) a[i] = As[(ty * 4 + i) * LDA + k];
            float4 b0 = *(const float4*)(Bs + k * FDIM + tx * 8);
            float4 b1v = *(const float4*)(Bs + k * FDIM + tx * 8 + 4);
            float b[8] = {b0.x, b0.y, b0.z, b0.w, b1v.x, b1v.y, b1v.z, b1v.w};
#pragma unroll
            for (int i = 0; i < 4; i++)
#pragma unroll
                for (int j = 0; j < 8; j++) acc[i][j] += a[i] * b[j];
        }
    }

    float4 bb0 = g_bias[tx * 2];
    float4 bb1 = g_bias[tx * 2 + 1];
    float bias[8] = {bb0.x, bb0.y, bb0.z, bb0.w, bb1.x, bb1.y, bb1.z, bb1.w};

#pragma unroll
    for (int i = 0; i < 4; i++) {
        int n = n0 + ty * 4 + i;
        if (n < NN) {
            float4* o = (float4*)(out + (size_t)n * FDIM + tx * 8);
            o[0] = make_float4(acc[i][0] + bias[0], acc[i][1] + bias[1],
                               acc[i][2] + bias[2], acc[i][3] + bias[3]);
            o[1] = make_float4(acc[i][4] + bias[4], acc[i][5] + bias[5],
                               acc[i][6] + bias[6], acc[i][7] + bias[7]);
        }
    }
}

extern "C" void kernel_launch(void* const* d_in, const int* in_sizes, int n_in,
                              void* d_out, int out_size) {
    const float* x          = (const float*)d_in[0];
    const int*   edge_index = (const int*)d_in[1];   // int32 (JAX x64 disabled)
    const int*   edge_type  = (const int*)d_in[2];   // int32
    const float* W_self     = (const float*)d_in[3];
    const float* b_self     = (const float*)d_in[4];
    const float* W1         = (const float*)d_in[5];
    const float* b1         = (const float*)d_in[6];
    const float* gamma      = (const float*)d_in[7];
    const float* beta       = (const float*)d_in[8];
    const float* W2         = (const float*)d_in[9];
    const float* b2         = (const float*)d_in[10];
    float* out = (float*)d_out;

    cudaFuncSetAttribute(k_gemm1, cudaFuncAttributeMaxDynamicSharedMemorySize, SMEM_BYTES);
    cudaFuncSetAttribute(k_gemm2, cudaFuncAttributeMaxDynamicSharedMemorySize, SMEM_BYTES);

    k_init<<<(NREL * NN * (FDIM / 4) + 255) / 256, 256>>>(x);
    k_zero_stats<<<1, 512>>>();
    k_scatter<<<(NE * 32 + 255) / 256, 256>>>(x, edge_index, edge_type);
    dim3 g1(NBLK, NREL);
    k_gemm1<<<g1, 256, SMEM_BYTES>>>(W1, b1);
    k_bn<<<1, 512>>>(gamma, beta, b_self, b2);
    k_gemm2<<<NBLK, 256, SMEM_BYTES>>>(x, W2, W_self, out);
}

// round 4
// speedup vs baseline: 1.7210x; 1.7210x over previous
#include <cuda_runtime.h>

#define NN 50000
#define NE 800000
#define FDIM 128
#define NREL 4
#define BN_EPS 1e-5f

#define TM 128
#define LDA 132
#define NBLK ((NN + TM - 1) / TM)   // 391
#define SMEM_BYTES ((TM * LDA + FDIM * FDIM) * 4)   // 133,120 B

// scratch (device globals; float4-typed for 16B alignment)
__device__ float4 g_h0[(size_t)NREL * NN * FDIM / 4];
__device__ float4 g_h1[(size_t)NREL * NN * FDIM / 4];
__device__ float  g_sum[NREL * FDIM];
__device__ float  g_sumsq[NREL * FDIM];
__device__ float4 g_scale[NREL * FDIM / 4];
__device__ float4 g_shift[NREL * FDIM / 4];
__device__ float4 g_bias[FDIM / 4];

// ---- packed f32x2 helpers (FFMA2 is PTX-only; ptxas never auto-fuses) ----
__device__ __forceinline__ void ffma2(unsigned long long& d,
                                      unsigned long long a,
                                      unsigned long long b) {
    asm("fma.rn.f32x2 %0, %1, %2, %0;" : "+l"(d) : "l"(a), "l"(b));
}
__device__ __forceinline__ unsigned long long bcast2(float x) {
    unsigned long long r;
    asm("mov.b64 %0, {%1, %1};" : "=l"(r) : "f"(x));
    return r;
}
__device__ __forceinline__ float2 unpk2(unsigned long long v) {
    float2 r;
    asm("mov.b64 {%0, %1}, %2;" : "=f"(r.x), "=f"(r.y) : "l"(v));
    return r;
}

// ---------------------------------------------------------------------------
// h0[r][n][:] = x[n][:]
// ---------------------------------------------------------------------------
__global__ void k_init(const float* __restrict__ x) {
    int i = blockIdx.x * blockDim.x + threadIdx.x;
    const int total = NREL * NN * (FDIM / 4);
    if (i >= total) return;
    const int per = NN * (FDIM / 4);
    g_h0[i] = ((const float4*)x)[i % per];
}

__global__ void k_zero_stats() {
    int i = threadIdx.x;
    if (i < NREL * FDIM) { g_sum[i] = 0.f; g_sumsq[i] = 0.f; }
}

// ---------------------------------------------------------------------------
// scatter: h0[rel][dst][:] += x[src][:]  (one warp per edge, vector RED)
// ---------------------------------------------------------------------------
__global__ void k_scatter(const float* __restrict__ x,
                          const int* __restrict__ edge_index,
                          const int* __restrict__ edge_type) {
    long long g = (long long)blockIdx.x * blockDim.x + threadIdx.x;
    if (g >= (long long)NE * 32) return;
    int e = (int)(g >> 5);
    int q = (int)(g & 31);
    int src = edge_index[e];
    int dst = edge_index[NE + e];
    int rel = edge_type[e];
    if ((unsigned)src >= NN || (unsigned)dst >= NN || (unsigned)rel >= NREL) return;
    float4 v = ((const float4*)(x + (size_t)src * FDIM))[q];
    float* p = (float*)g_h0 + ((size_t)rel * NN + (size_t)dst) * FDIM + q * 4;
    asm volatile("red.global.add.v4.f32 [%0], {%1, %2, %3, %4};"
                 :: "l"(__cvta_generic_to_global(p)),
                    "f"(v.x), "f"(v.y), "f"(v.z), "f"(v.w)
                 : "memory");
}

// ---------------------------------------------------------------------------
// shared 128x128x128 FFMA2 micro-kernel pieces
// thread (tx = tid&15, ty = tid>>4): rows ty*8..+7, cols {tx*4..+3, 64+tx*4..+3}
// acc[i][p]: p=0,1 -> cols tx*4+2p{,+1}; p=2,3 -> cols 64+tx*4+2(p-2){,+1}
// ---------------------------------------------------------------------------
#define KLOOP(As, Bs, acc, tx, ty)                                             \
    _Pragma("unroll 1")                                                        \
    for (int kk = 0; kk < FDIM; kk += 4) {                                     \
        float4 a[8];                                                           \
        _Pragma("unroll")                                                      \
        for (int i = 0; i < 8; i++)                                            \
            a[i] = *(const float4*)((As) + ((ty) * 8 + i) * LDA + kk);         \
        _Pragma("unroll")                                                      \
        for (int u = 0; u < 4; u++) {                                          \
            ulonglong2 b0 = *(const ulonglong2*)((Bs) + (kk + u) * FDIM + (tx) * 4);      \
            ulonglong2 b1 = *(const ulonglong2*)((Bs) + (kk + u) * FDIM + 64 + (tx) * 4); \
            _Pragma("unroll")                                                  \
            for (int i = 0; i < 8; i++) {                                      \
                float av = (u == 0) ? a[i].x : (u == 1) ? a[i].y                \
                          : (u == 2) ? a[i].z : a[i].w;                         \
                unsigned long long aa = bcast2(av);                            \
                ffma2(acc[i][0], aa, b0.x);                                    \
                ffma2(acc[i][1], aa, b0.y);                                    \
                ffma2(acc[i][2], aa, b1.x);                                    \
                ffma2(acc[i][3], aa, b1.y);                                    \
            }                                                                  \
        }                                                                      \
    }

// ---------------------------------------------------------------------------
// GEMM1: h1[r] = h0[r] @ W1[r] + b1[r]; fused BN sum/sumsq
// ---------------------------------------------------------------------------
__global__ void __launch_bounds__(256, 1) k_gemm1(const float* __restrict__ W1,
                                                  const float* __restrict__ b1) {
    extern __shared__ float smem[];
    float* As = smem;                  // [128][LDA]
    float* Bs = smem + TM * LDA;       // [128][128]
    const int r = blockIdx.y;
    const int n0 = blockIdx.x * TM;
    const int tid = threadIdx.x;
    const int tx = tid & 15;
    const int ty = tid >> 4;

    const float* A = (const float*)g_h0 + (size_t)r * NN * FDIM;
    const float4* B4 = (const float4*)(W1 + r * FDIM * FDIM);

#pragma unroll
    for (int i = 0; i < 16; i++)
        ((float4*)Bs)[i * 256 + tid] = B4[i * 256 + tid];

#pragma unroll
    for (int i = 0; i < 16; i++) {
        int idx = i * 256 + tid;
        int row = idx >> 5, c4 = idx & 31;
        float4 v = make_float4(0.f, 0.f, 0.f, 0.f);
        int n = n0 + row;
        if (n < NN) v = ((const float4*)(A + (size_t)n * FDIM))[c4];
        *(float4*)(As + row * LDA + c4 * 4) = v;
    }
    __syncthreads();

    unsigned long long acc[8][4];
#pragma unroll
    for (int i = 0; i < 8; i++)
#pragma unroll
        for (int p = 0; p < 4; p++) acc[i][p] = 0ull;

    KLOOP(As, Bs, acc, tx, ty)

    __syncthreads();   // k-loop tile reads done; smem reused for reduction

    const float* b1p = b1 + r * FDIM;
    float4 bias0 = *(const float4*)(b1p + tx * 4);
    float4 bias1 = *(const float4*)(b1p + 64 + tx * 4);

    float s[8], q[8];
#pragma unroll
    for (int j = 0; j < 8; j++) { s[j] = 0.f; q[j] = 0.f; }

    float* Hout = (float*)g_h1 + (size_t)r * NN * FDIM;
#pragma unroll
    for (int i = 0; i < 8; i++) {
        int n = n0 + ty * 8 + i;
        if (n < NN) {
            float2 p0 = unpk2(acc[i][0]), p1 = unpk2(acc[i][1]);
            float2 p2 = unpk2(acc[i][2]), p3 = unpk2(acc[i][3]);
            float v[8] = {p0.x + bias0.x, p0.y + bias0.y, p1.x + bias0.z, p1.y + bias0.w,
                          p2.x + bias1.x, p2.y + bias1.y, p3.x + bias1.z, p3.y + bias1.w};
#pragma unroll
            for (int j = 0; j < 8; j++) { s[j] += v[j]; q[j] += v[j] * v[j]; }
            float4* o0 = (float4*)(Hout + (size_t)n * FDIM + tx * 4);
            float4* o1 = (float4*)(Hout + (size_t)n * FDIM + 64 + tx * 4);
            *o0 = make_float4(v[0], v[1], v[2], v[3]);
            *o1 = make_float4(v[4], v[5], v[6], v[7]);
        }
    }

    // column reduce over 16 ty-groups, then one atomic per column
    float* redS = As;   // [16][128]
    float* redQ = Bs;   // [16][128]
#pragma unroll
    for (int j = 0; j < 4; j++) {
        redS[ty * FDIM + tx * 4 + j] = s[j];
        redQ[ty * FDIM + tx * 4 + j] = q[j];
        redS[ty * FDIM + 64 + tx * 4 + j] = s[4 + j];
        redQ[ty * FDIM + 64 + tx * 4 + j] = q[4 + j];
    }
#pragma unroll
    for (int off = 8; off > 0; off >>= 1) {
        __syncthreads();
        if (ty < off) {
#pragma unroll
            for (int j = 0; j < 4; j++) {
                int c0 = tx * 4 + j, c1 = 64 + tx * 4 + j;
                redS[ty * FDIM + c0] += redS[(ty + off) * FDIM + c0];
                redQ[ty * FDIM + c0] += redQ[(ty + off) * FDIM + c0];
                redS[ty * FDIM + c1] += redS[(ty + off) * FDIM + c1];
                redQ[ty * FDIM + c1] += redQ[(ty + off) * FDIM + c1];
            }
        }
    }
    __syncthreads();
    if (ty == 0) {
#pragma unroll
        for (int j = 0; j < 4; j++) {
            int c0 = tx * 4 + j, c1 = 64 + tx * 4 + j;
            atomicAdd(&g_sum[r * FDIM + c0], redS[c0]);
            atomicAdd(&g_sumsq[r * FDIM + c0], redQ[c0]);
            atomicAdd(&g_sum[r * FDIM + c1], redS[c1]);
            atomicAdd(&g_sumsq[r * FDIM + c1], redQ[c1]);
        }
    }
}

// ---------------------------------------------------------------------------
// BN scale/shift + folded output biases
// ---------------------------------------------------------------------------
__global__ void k_bn(const float* __restrict__ gamma, const float* __restrict__ beta,
                     const float* __restrict__ b_self, const float* __restrict__ b2) {
    int i = threadIdx.x;
    if (i < NREL * FDIM) {
        const float invN = 1.f / (float)NN;
        float mean = g_sum[i] * invN;
        float var = g_sumsq[i] * invN - mean * mean;
        float sc = gamma[i] * rsqrtf(var + BN_EPS);
        ((float*)g_scale)[i] = sc;
        ((float*)g_shift)[i] = beta[i] - mean * sc;
    }
    if (i < FDIM) {
        float b = b_self[i];
#pragma unroll
        for (int r = 0; r < NREL; r++) b += b2[r * FDIM + i];
        ((float*)g_bias)[i] = b;
    }
}

// ---------------------------------------------------------------------------
// GEMM2 (K=640): out = sum_r relu(bn(h1[r])) @ W2[r] + x @ W_self + g_bias
// ---------------------------------------------------------------------------
__global__ void __launch_bounds__(256, 1) k_gemm2(const float* __restrict__ x,
                                                  const float* __restrict__ W2,
                                                  const float* __restrict__ W_self,
                                                  float* __restrict__ out) {
    extern __shared__ float smem[];
    float* As = smem;
    float* Bs = smem + TM * LDA;
    const int n0 = blockIdx.x * TM;
    const int tid = threadIdx.x;
    const int tx = tid & 15;
    const int ty = tid >> 4;

    unsigned long long acc[8][4];
#pragma unroll
    for (int i = 0; i < 8; i++)
#pragma unroll
        for (int p = 0; p < 4; p++) acc[i][p] = 0ull;

    for (int r = 0; r < NREL + 1; r++) {
        __syncthreads();

        const float4* B4 = (r < NREL) ? (const float4*)(W2 + r * FDIM * FDIM)
                                      : (const float4*)W_self;
#pragma unroll
        for (int i = 0; i < 16; i++)
            ((float4*)Bs)[i * 256 + tid] = B4[i * 256 + tid];

        if (r < NREL) {
            const float* H = (const float*)g_h1 + (size_t)r * NN * FDIM;
            const float4* sc4 = g_scale + r * (FDIM / 4);
            const float4* sh4 = g_shift + r * (FDIM / 4);
#pragma unroll
            for (int i = 0; i < 16; i++) {
                int idx = i * 256 + tid;
                int row = idx >> 5, c4 = idx & 31;
                float4 v = make_float4(0.f, 0.f, 0.f, 0.f);
                int n = n0 + row;
                if (n < NN) {
                    v = ((const float4*)(H + (size_t)n * FDIM))[c4];
                    float4 sc = sc4[c4], sh = sh4[c4];
                    v.x = fmaxf(v.x * sc.x + sh.x, 0.f);
                    v.y = fmaxf(v.y * sc.y + sh.y, 0.f);
                    v.z = fmaxf(v.z * sc.z + sh.z, 0.f);
                    v.w = fmaxf(v.w * sc.w + sh.w, 0.f);
                }
                *(float4*)(As + row * LDA + c4 * 4) = v;
            }
        } else {
#pragma unroll
            for (int i = 0; i < 16; i++) {
                int idx = i * 256 + tid;
                int row = idx >> 5, c4 = idx & 31;
                float4 v = make_float4(0.f, 0.f, 0.f, 0.f);
                int n = n0 + row;
                if (n < NN) v = ((const float4*)(x + (size_t)n * FDIM))[c4];
                *(float4*)(As + row * LDA + c4 * 4) = v;
            }
        }
        __syncthreads();

        KLOOP(As, Bs, acc, tx, ty)
    }

    float4 bias0 = g_bias[tx];
    float4 bias1 = g_bias[16 + tx];

#pragma unroll
    for (int i = 0; i < 8; i++) {
        int n = n0 + ty * 8 + i;
        if (n < NN) {
            float2 p0 = unpk2(acc[i][0]), p1 = unpk2(acc[i][1]);
            float2 p2 = unpk2(acc[i][2]), p3 = unpk2(acc[i][3]);
            float4* o0 = (float4*)(out + (size_t)n * FDIM + tx * 4);
            float4* o1 = (float4*)(out + (size_t)n * FDIM + 64 + tx * 4);
            *o0 = make_float4(p0.x + bias0.x, p0.y + bias0.y,
                              p1.x + bias0.z, p1.y + bias0.w);
            *o1 = make_float4(p2.x + bias1.x, p2.y + bias1.y,
                              p3.x + bias1.z, p3.y + bias1.w);
        }
    }
}

extern "C" void kernel_launch(void* const* d_in, const int* in_sizes, int n_in,
                              void* d_out, int out_size) {
    const float* x          = (const float*)d_in[0];
    const int*   edge_index = (const int*)d_in[1];   // int32 (JAX x64 disabled)
    const int*   edge_type  = (const int*)d_in[2];
    const float* W_self     = (const float*)d_in[3];
    const float* b_self     = (const float*)d_in[4];
    const float* W1         = (const float*)d_in[5];
    const float* b1         = (const float*)d_in[6];
    const float* gamma      = (const float*)d_in[7];
    const float* beta       = (const float*)d_in[8];
    const float* W2         = (const float*)d_in[9];
    const float* b2         = (const float*)d_in[10];
    float* out = (float*)d_out;

    cudaFuncSetAttribute(k_gemm1, cudaFuncAttributeMaxDynamicSharedMemorySize, SMEM_BYTES);
    cudaFuncSetAttribute(k_gemm2, cudaFuncAttributeMaxDynamicSharedMemorySize, SMEM_BYTES);

    k_init<<<(NREL * NN * (FDIM / 4) + 255) / 256, 256>>>(x);
    k_zero_stats<<<1, 512>>>();
    k_scatter<<<(NE * 32 + 255) / 256, 256>>>(x, edge_index, edge_type);
    dim3 g1(NBLK, NREL);
    k_gemm1<<<g1, 256, SMEM_BYTES>>>(W1, b1);
    k_bn<<<1, 512>>>(gamma, beta, b_self, b2);
    k_gemm2<<<NBLK, 256, SMEM_BYTES>>>(x, W2, W_self, out);
}